// round 9
// baseline (speedup 1.0000x reference)
#include <cuda_runtime.h>
#include <cuda_bf16.h>
#include <cstdint>

// Problem constants
constexpr int BATCH = 2048;
constexpr int NF    = 512;
constexpr int FD    = 64;
constexpr int NOUT  = 8;
constexpr int BM    = 128;   // M-tile per block
constexpr int SLAB  = 256;   // batch rows per depth-first slab (32 MB fp32)

// fp32 activation ping-pong (2 x 256 MB)
__device__ __align__(256) float g_x0[BATCH * NF * FD];
__device__ __align__(256) float g_x1[BATCH * NF * FD];
// Pre-split transposed weights: Wt[n][k] = W[k][n], bf16 hi/lo planes.
// Per fold: 64 rows(n) x 64 k packed as 512 uint4 (8 bf16 each).
__device__ __align__(256) uint4 g_wh[4 * 512 * 512];
__device__ __align__(256) uint4 g_wl[4 * 512 * 512];

// SW128 swizzle (Swizzle<3,4,3>) on byte offsets with 128B rows
#define SW(o) ((o) ^ ((((unsigned)(o)) >> 3) & 0x70))

__device__ __forceinline__ uint32_t smem_u32(const void* p) {
    uint32_t a;
    asm("{ .reg .u64 t; cvta.to.shared.u64 t, %1; cvt.u32.u64 %0, t; }" : "=r"(a) : "l"(p));
    return a;
}
__device__ __forceinline__ uint32_t pack_hi_lo(float a, float b, uint32_t& lo) {
    __nv_bfloat162 h2 = __floats2bfloat162_rn(a, b);
    float ra = a - __bfloat162float(h2.x);
    float rb = b - __bfloat162float(h2.y);
    __nv_bfloat162 l2 = __floats2bfloat162_rn(ra, rb);
    lo = *reinterpret_cast<uint32_t*>(&l2);
    return *reinterpret_cast<uint32_t*>(&h2);
}
__device__ __forceinline__ void ldsm_x4(uint32_t* r, uint32_t addr) {
    asm volatile("ldmatrix.sync.aligned.m8n8.x4.shared.b16 {%0,%1,%2,%3}, [%4];"
                 : "=r"(r[0]), "=r"(r[1]), "=r"(r[2]), "=r"(r[3]) : "r"(addr));
}
__device__ __forceinline__ void mma_bf16(float* c, const uint32_t* a,
                                         uint32_t b0, uint32_t b1) {
    asm volatile(
        "mma.sync.aligned.m16n8k16.row.col.f32.bf16.bf16.f32 "
        "{%0,%1,%2,%3}, {%4,%5,%6,%7}, {%8,%9}, {%0,%1,%2,%3};"
        : "+f"(c[0]), "+f"(c[1]), "+f"(c[2]), "+f"(c[3])
        : "r"(a[0]), "r"(a[1]), "r"(a[2]), "r"(a[3]), "r"(b0), "r"(b1));
}

// ---------------- weight prep: transpose + bf16 hi/lo split ----------------
__global__ void wprep_kernel(const float* __restrict__ W) {
    __shared__ float s[64][65];
    const int lf = blockIdx.x;                 // layer*512 + fold
    const float4* Wf4 = reinterpret_cast<const float4*>(W + (size_t)lf * 4096);
    for (int i = threadIdx.x; i < 1024; i += 256) {
        const int k = i >> 4, nq = i & 15;
        float4 v = Wf4[i];
        s[k][nq * 4 + 0] = v.x; s[k][nq * 4 + 1] = v.y;
        s[k][nq * 4 + 2] = v.z; s[k][nq * 4 + 3] = v.w;
    }
    __syncthreads();
    for (int i = threadIdx.x; i < 512; i += 256) {
        const int n = i >> 3, kq = i & 7;      // out row n, 8-k chunk kq
        uint32_t hw[4], lw[4];
        #pragma unroll
        for (int j = 0; j < 4; j++) {
            const float a = s[kq * 8 + j * 2 + 0][n];
            const float b = s[kq * 8 + j * 2 + 1][n];
            hw[j] = pack_hi_lo(a, b, lw[j]);
        }
        g_wh[(size_t)lf * 512 + i] = make_uint4(hw[0], hw[1], hw[2], hw[3]);
        g_wl[(size_t)lf * 512 + i] = make_uint4(lw[0], lw[1], lw[2], lw[3]);
    }
}

// ---------------- HMMA layer kernel (256 threads, 8 warps — R7 config) -----
// Dynamic smem map (bytes): HH 0 (16K), HL 16384 (16K), WH 32768 (8K), WL 40960 (8K).
constexpr int SM_HH = 0, SM_HL = 16384, SM_WH = 32768, SM_WL = 40960;
constexpr int SMEM_BYTES = 49152;

__global__ __launch_bounds__(256, 2)
void layer_mma_kernel(const float* __restrict__ xin,   // slab base (row 0 of slab)
                      const uint4* __restrict__ wh,    // this layer: [512 folds][512] uint4
                      const uint4* __restrict__ wl,
                      const int*   __restrict__ fidx,
                      float*       __restrict__ xout)  // slab base
{
    extern __shared__ char smem[];
    const uint32_t sb = smem_u32(smem);
    const int tid = threadIdx.x, wid = tid >> 5, lid = tid & 31;
    const int f = blockIdx.x, m0 = blockIdx.y * BM;

    // --- W tiles (pre-transposed bf16 hi/lo): copy with SW128 swizzle ---
    const uint4* whf = wh + (size_t)f * 512;
    const uint4* wlf = wl + (size_t)f * 512;
    #pragma unroll
    for (int it = 0; it < 2; it++) {
        const int i = it * 256 + tid;          // 0..511
        const int n = i >> 3, q = i & 7;
        const uint32_t off = SW(n * 128 + q * 16);
        *reinterpret_cast<uint4*>(smem + SM_WH + off) = whf[i];
        *reinterpret_cast<uint4*>(smem + SM_WL + off) = wlf[i];
    }

    // --- H tiles: gather + product (fp32), split to bf16 hi/lo, swizzled store ---
    const float* x0 = xin + (size_t)fidx[2 * f + 0] * FD;
    const float* x1 = xin + (size_t)fidx[2 * f + 1] * FD;
    #pragma unroll
    for (int it = 0; it < 4; it++) {
        const int i = it * 256 + tid;          // 0..1023
        const int m = i >> 3, q = i & 7;       // row m (0..127), 8-k chunk q
        const size_t boff = (size_t)(m0 + m) * (NF * FD) + q * 8;
        const float4 a0 = *reinterpret_cast<const float4*>(x0 + boff);
        const float4 a1 = *reinterpret_cast<const float4*>(x0 + boff + 4);
        const float4 b0 = *reinterpret_cast<const float4*>(x1 + boff);
        const float4 b1 = *reinterpret_cast<const float4*>(x1 + boff + 4);
        const float p[8] = { a0.x * b0.x, a0.y * b0.y, a0.z * b0.z, a0.w * b0.w,
                             a1.x * b1.x, a1.y * b1.y, a1.z * b1.z, a1.w * b1.w };
        uint32_t hw[4], lw[4];
        #pragma unroll
        for (int j = 0; j < 4; j++)
            hw[j] = pack_hi_lo(p[2 * j], p[2 * j + 1], lw[j]);
        const uint32_t off = SW(m * 128 + q * 16);
        *reinterpret_cast<uint4*>(smem + SM_HH + off) = make_uint4(hw[0], hw[1], hw[2], hw[3]);
        *reinterpret_cast<uint4*>(smem + SM_HL + off) = make_uint4(lw[0], lw[1], lw[2], lw[3]);
    }
    __syncthreads();

    // --- warp-tiled MMA: 8 warps, warp tile 32(M) x 32(N) ---
    const int wm = wid >> 1;                   // 0..3 -> m offset wm*32
    const int wn = wid & 1;                    // 0..1 -> n offset wn*32
    const int l7 = lid & 7, l8 = (lid >> 3) & 1, l16 = lid >> 4;

    float acc[2][4][4];                        // [mt][nt][frag]
    #pragma unroll
    for (int mt = 0; mt < 2; mt++)
        #pragma unroll
        for (int nt = 0; nt < 4; nt++)
            #pragma unroll
            for (int j = 0; j < 4; j++)
                acc[mt][nt][j] = 0.0f;

    #pragma unroll
    for (int ks = 0; ks < 4; ks++) {
        const int kc = ks * 16 + l16 * 8;      // k column for this lane's ldmatrix
        uint32_t AH[2][4], AL[2][4], BH[2][4], BL[2][4];
        #pragma unroll
        for (int mt = 0; mt < 2; mt++) {
            const int row = wm * 32 + mt * 16 + l7 + l8 * 8;
            const uint32_t off = SW(row * 128 + kc * 2);
            ldsm_x4(AH[mt], sb + SM_HH + off);
            ldsm_x4(AL[mt], sb + SM_HL + off);
        }
        #pragma unroll
        for (int h = 0; h < 2; h++) {
            const int n = wn * 32 + h * 16 + l7 + l8 * 8;
            const uint32_t off = SW(n * 128 + kc * 2);
            ldsm_x4(BH[h], sb + SM_WH + off);
            ldsm_x4(BL[h], sb + SM_WL + off);
        }
        #pragma unroll
        for (int mt = 0; mt < 2; mt++)
            #pragma unroll
            for (int nt = 0; nt < 4; nt++) {
                const int h = nt >> 1, s = nt & 1;
                mma_bf16(acc[mt][nt], AH[mt], BH[h][s], BH[h][s + 2]);
                mma_bf16(acc[mt][nt], AH[mt], BL[h][s], BL[h][s + 2]);
                mma_bf16(acc[mt][nt], AL[mt], BH[h][s], BH[h][s + 2]);
            }
    }

    // --- epilogue: fragment -> GMEM (float2 stores, 128B per row per warp) ---
    const int quad = lid >> 2, qlane = lid & 3;
    #pragma unroll
    for (int mt = 0; mt < 2; mt++) {
        const int r = m0 + wm * 32 + mt * 16 + quad;
        #pragma unroll
        for (int nt = 0; nt < 4; nt++) {
            const int col = f * FD + wn * 32 + nt * 8 + qlane * 2;
            float* d0 = xout + (size_t)r * (NF * FD) + col;
            float* d1 = d0 + (size_t)8 * (NF * FD);
            *reinterpret_cast<float2*>(d0) = make_float2(acc[mt][nt][0], acc[mt][nt][1]);
            *reinterpret_cast<float2*>(d1) = make_float2(acc[mt][nt][2], acc[mt][nt][3]);
        }
    }
}

// Final gather: out[b, o, :] = x[b, out_idx[o], :]
__global__ void gather_kernel(const float* __restrict__ x,
                              const int* __restrict__ oidx,
                              float* __restrict__ out)
{
    const int t = blockIdx.x * blockDim.x + threadIdx.x;
    const int total = BATCH * NOUT * (FD / 4);
    if (t >= total) return;
    const int q = t & 15;
    const int o = (t >> 4) & (NOUT - 1);
    const int b = t >> 7;
    const size_t src = (size_t)b * (NF * FD) + (size_t)oidx[o] * FD + q * 4;
    reinterpret_cast<float4*>(out)[t] = *reinterpret_cast<const float4*>(x + src);
}

extern "C" void kernel_launch(void* const* d_in, const int* in_sizes, int n_in,
                              void* d_out, int out_size)
{
    const float* in_graph = (const float*)d_in[0];
    const float* weights  = (const float*)d_in[1];
    const int*   fold_idx = (const int*)d_in[2];
    const int*   out_idx  = (const int*)d_in[3];
    float*       out      = (float*)d_out;

    float *p0 = nullptr, *p1 = nullptr;
    uint4 *wh = nullptr, *wl = nullptr;
    cudaGetSymbolAddress((void**)&p0, g_x0);
    cudaGetSymbolAddress((void**)&p1, g_x1);
    cudaGetSymbolAddress((void**)&wh, g_wh);
    cudaGetSymbolAddress((void**)&wl, g_wl);

    cudaFuncSetAttribute(layer_mma_kernel,
                         cudaFuncAttributeMaxDynamicSharedMemorySize, SMEM_BYTES);

    // Pre-split + transpose all layer weights into bf16 hi/lo
    wprep_kernel<<<4 * 512, 256>>>(weights);

    const size_t wlayer   = (size_t)512 * 512;     // uint4 per layer
    const size_t i_stride = (size_t)NF * 2;        // ints per layer
    const size_t slab_elm = (size_t)SLAB * NF * FD;

    dim3 grid(NF, SLAB / BM);                      // (512, 2) per slab-layer
    dim3 block(256);

    // Depth-first over batch slabs: slab stays L2-resident across the 4 layers.
    for (int s = 0; s < BATCH / SLAB; s++) {
        const float* in0 = in_graph + s * slab_elm;
        float* a0 = p0 + s * slab_elm;
        float* a1 = p1 + s * slab_elm;

        layer_mma_kernel<<<grid, block, SMEM_BYTES>>>(in0, wh + 0 * wlayer, wl + 0 * wlayer,
                                                      fold_idx + 0 * i_stride, a0);
        layer_mma_kernel<<<grid, block, SMEM_BYTES>>>(a0, wh + 1 * wlayer, wl + 1 * wlayer,
                                                      fold_idx + 1 * i_stride, a1);
        layer_mma_kernel<<<grid, block, SMEM_BYTES>>>(a1, wh + 2 * wlayer, wl + 2 * wlayer,
                                                      fold_idx + 2 * i_stride, a0);
        layer_mma_kernel<<<grid, block, SMEM_BYTES>>>(a0, wh + 3 * wlayer, wl + 3 * wlayer,
                                                      fold_idx + 3 * i_stride, a1);
    }

    const int total = BATCH * NOUT * (FD / 4);
    gather_kernel<<<(total + 255) / 256, 256>>>(p1, out_idx, out);
}

// round 10
// speedup vs baseline: 1.0970x; 1.0970x over previous
#include <cuda_runtime.h>
#include <cuda_bf16.h>
#include <cstdint>

// Problem constants
constexpr int BATCH = 2048;
constexpr int NF    = 512;
constexpr int FD    = 64;
constexpr int NOUT  = 8;
constexpr int BM    = 128;   // M-tile per block-iteration
constexpr int NT    = 4;     // m-tiles per CTA (B-fragments reused across them)

// fp32 activation ping-pong (2 x 256 MB)
__device__ __align__(256) float g_x0[BATCH * NF * FD];
__device__ __align__(256) float g_x1[BATCH * NF * FD];
// Pre-split transposed weights: Wt[n][k] = W[k][n], bf16 hi/lo planes.
// Per fold: 64 rows(n) x 64 k packed as 512 uint4 (8 bf16 each).
__device__ __align__(256) uint4 g_wh[4 * 512 * 512];
__device__ __align__(256) uint4 g_wl[4 * 512 * 512];

// SW128 swizzle (Swizzle<3,4,3>) on byte offsets with 128B rows
#define SW(o) ((o) ^ ((((unsigned)(o)) >> 3) & 0x70))

__device__ __forceinline__ uint32_t smem_u32(const void* p) {
    uint32_t a;
    asm("{ .reg .u64 t; cvta.to.shared.u64 t, %1; cvt.u32.u64 %0, t; }" : "=r"(a) : "l"(p));
    return a;
}
__device__ __forceinline__ uint32_t pack_hi_lo(float a, float b, uint32_t& lo) {
    __nv_bfloat162 h2 = __floats2bfloat162_rn(a, b);
    float ra = a - __bfloat162float(h2.x);
    float rb = b - __bfloat162float(h2.y);
    __nv_bfloat162 l2 = __floats2bfloat162_rn(ra, rb);
    lo = *reinterpret_cast<uint32_t*>(&l2);
    return *reinterpret_cast<uint32_t*>(&h2);
}
__device__ __forceinline__ void ldsm_x4(uint32_t* r, uint32_t addr) {
    asm volatile("ldmatrix.sync.aligned.m8n8.x4.shared.b16 {%0,%1,%2,%3}, [%4];"
                 : "=r"(r[0]), "=r"(r[1]), "=r"(r[2]), "=r"(r[3]) : "r"(addr));
}
__device__ __forceinline__ void mma_bf16(float* c, const uint32_t* a,
                                         uint32_t b0, uint32_t b1) {
    asm volatile(
        "mma.sync.aligned.m16n8k16.row.col.f32.bf16.bf16.f32 "
        "{%0,%1,%2,%3}, {%4,%5,%6,%7}, {%8,%9}, {%0,%1,%2,%3};"
        : "+f"(c[0]), "+f"(c[1]), "+f"(c[2]), "+f"(c[3])
        : "r"(a[0]), "r"(a[1]), "r"(a[2]), "r"(a[3]), "r"(b0), "r"(b1));
}

// ---------------- weight prep: transpose + bf16 hi/lo split ----------------
__global__ void wprep_kernel(const float* __restrict__ W) {
    __shared__ float s[64][65];
    const int lf = blockIdx.x;                 // layer*512 + fold
    const float4* Wf4 = reinterpret_cast<const float4*>(W + (size_t)lf * 4096);
    for (int i = threadIdx.x; i < 1024; i += 256) {
        const int k = i >> 4, nq = i & 15;
        float4 v = Wf4[i];
        s[k][nq * 4 + 0] = v.x; s[k][nq * 4 + 1] = v.y;
        s[k][nq * 4 + 2] = v.z; s[k][nq * 4 + 3] = v.w;
    }
    __syncthreads();
    for (int i = threadIdx.x; i < 512; i += 256) {
        const int n = i >> 3, kq = i & 7;      // out row n, 8-k chunk kq
        uint32_t hw[4], lw[4];
        #pragma unroll
        for (int j = 0; j < 4; j++) {
            const float a = s[kq * 8 + j * 2 + 0][n];
            const float b = s[kq * 8 + j * 2 + 1][n];
            hw[j] = pack_hi_lo(a, b, lw[j]);
        }
        g_wh[(size_t)lf * 512 + i] = make_uint4(hw[0], hw[1], hw[2], hw[3]);
        g_wl[(size_t)lf * 512 + i] = make_uint4(lw[0], lw[1], lw[2], lw[3]);
    }
}

// ---------------- HMMA layer kernel: 8 warps, 4 m-tiles/CTA ----------------
// Dynamic smem map (bytes): HH 0 (16K), HL 16384 (16K), WH 32768 (8K), WL 40960 (8K).
constexpr int SM_HH = 0, SM_HL = 16384, SM_WH = 32768, SM_WL = 40960;
constexpr int SMEM_BYTES = 49152;

__global__ __launch_bounds__(256, 2)
void layer_mma_kernel(const float* __restrict__ xin,
                      const uint4* __restrict__ wh,   // this layer: [512 folds][512] uint4
                      const uint4* __restrict__ wl,
                      const int*   __restrict__ fidx,
                      float*       __restrict__ xout)
{
    extern __shared__ char smem[];
    const uint32_t sb = smem_u32(smem);
    const int tid = threadIdx.x, wid = tid >> 5, lid = tid & 31;
    const int f = blockIdx.x;

    // --- W tiles (pre-transposed bf16 hi/lo): copy with SW128 swizzle, ONCE ---
    const uint4* whf = wh + (size_t)f * 512;
    const uint4* wlf = wl + (size_t)f * 512;
    #pragma unroll
    for (int it = 0; it < 2; it++) {
        const int i = it * 256 + tid;          // 0..511
        const int n = i >> 3, q = i & 7;
        const uint32_t off = SW(n * 128 + q * 16);
        *reinterpret_cast<uint4*>(smem + SM_WH + off) = whf[i];
        *reinterpret_cast<uint4*>(smem + SM_WL + off) = wlf[i];
    }
    __syncthreads();

    const int wm = wid >> 1;                   // 0..3 -> m offset wm*32
    const int wn = wid & 1;                    // 0..1 -> n offset wn*32
    const int l7 = lid & 7, l8 = (lid >> 3) & 1, l16 = lid >> 4;

    // --- B fragments: ldmatrix ONCE, held in registers for all m-tiles ---
    uint32_t BH[4][2][4], BL[4][2][4];         // [ks][h][frag] = 64 regs
    #pragma unroll
    for (int ks = 0; ks < 4; ks++) {
        const int kc = ks * 16 + l16 * 8;
        #pragma unroll
        for (int h = 0; h < 2; h++) {
            const int n = wn * 32 + h * 16 + l7 + l8 * 8;
            const uint32_t off = SW(n * 128 + kc * 2);
            ldsm_x4(BH[ks][h], sb + SM_WH + off);
            ldsm_x4(BL[ks][h], sb + SM_WL + off);
        }
    }

    const float* x0 = xin + (size_t)fidx[2 * f + 0] * FD;
    const float* x1 = xin + (size_t)fidx[2 * f + 1] * FD;
    const int quad = lid >> 2, qlane = lid & 3;

    #pragma unroll 1
    for (int t = 0; t < NT; t++) {
        const int m0 = blockIdx.y * BM + t * 512;   // 4 y-groups x 4 t = 2048 rows

        if (t > 0) __syncthreads();            // prior A-reads done before overwrite

        // --- H tile: gather + product (fp32), split hi/lo, swizzled store ---
        #pragma unroll
        for (int it = 0; it < 4; it++) {
            const int i = it * 256 + tid;      // 0..1023
            const int m = i >> 3, q = i & 7;   // row m (0..127), 8-k chunk q
            const size_t boff = (size_t)(m0 + m) * (NF * FD) + q * 8;
            const float4 a0 = *reinterpret_cast<const float4*>(x0 + boff);
            const float4 a1 = *reinterpret_cast<const float4*>(x0 + boff + 4);
            const float4 b0 = *reinterpret_cast<const float4*>(x1 + boff);
            const float4 b1 = *reinterpret_cast<const float4*>(x1 + boff + 4);
            const float p[8] = { a0.x * b0.x, a0.y * b0.y, a0.z * b0.z, a0.w * b0.w,
                                 a1.x * b1.x, a1.y * b1.y, a1.z * b1.z, a1.w * b1.w };
            uint32_t hw[4], lw[4];
            #pragma unroll
            for (int j = 0; j < 4; j++)
                hw[j] = pack_hi_lo(p[2 * j], p[2 * j + 1], lw[j]);
            const uint32_t off = SW(m * 128 + q * 16);
            *reinterpret_cast<uint4*>(smem + SM_HH + off) = make_uint4(hw[0], hw[1], hw[2], hw[3]);
            *reinterpret_cast<uint4*>(smem + SM_HL + off) = make_uint4(lw[0], lw[1], lw[2], lw[3]);
        }
        __syncthreads();

        // --- warp-tiled MMA: warp tile 32(M) x 32(N), B from registers ---
        float acc[2][4][4];
        #pragma unroll
        for (int mt = 0; mt < 2; mt++)
            #pragma unroll
            for (int nt = 0; nt < 4; nt++)
                #pragma unroll
                for (int j = 0; j < 4; j++)
                    acc[mt][nt][j] = 0.0f;

        #pragma unroll
        for (int ks = 0; ks < 4; ks++) {
            const int kc = ks * 16 + l16 * 8;
            uint32_t AH[2][4], AL[2][4];
            #pragma unroll
            for (int mt = 0; mt < 2; mt++) {
                const int row = wm * 32 + mt * 16 + l7 + l8 * 8;
                const uint32_t off = SW(row * 128 + kc * 2);
                ldsm_x4(AH[mt], sb + SM_HH + off);
                ldsm_x4(AL[mt], sb + SM_HL + off);
            }
            #pragma unroll
            for (int mt = 0; mt < 2; mt++)
                #pragma unroll
                for (int nt = 0; nt < 4; nt++) {
                    const int h = nt >> 1, s = nt & 1;
                    mma_bf16(acc[mt][nt], AH[mt], BH[ks][h][s], BH[ks][h][s + 2]);
                    mma_bf16(acc[mt][nt], AH[mt], BL[ks][h][s], BL[ks][h][s + 2]);
                    mma_bf16(acc[mt][nt], AL[mt], BH[ks][h][s], BH[ks][h][s + 2]);
                }
        }

        // --- epilogue: fragment -> GMEM (float2 stores) ---
        #pragma unroll
        for (int mt = 0; mt < 2; mt++) {
            const int r = m0 + wm * 32 + mt * 16 + quad;
            #pragma unroll
            for (int nt = 0; nt < 4; nt++) {
                const int col = f * FD + wn * 32 + nt * 8 + qlane * 2;
                float* d0 = xout + (size_t)r * (NF * FD) + col;
                float* d1 = d0 + (size_t)8 * (NF * FD);
                *reinterpret_cast<float2*>(d0) = make_float2(acc[mt][nt][0], acc[mt][nt][1]);
                *reinterpret_cast<float2*>(d1) = make_float2(acc[mt][nt][2], acc[mt][nt][3]);
            }
        }
    }
}

// Final gather: out[b, o, :] = x[b, out_idx[o], :]
__global__ void gather_kernel(const float* __restrict__ x,
                              const int* __restrict__ oidx,
                              float* __restrict__ out)
{
    const int t = blockIdx.x * blockDim.x + threadIdx.x;
    const int total = BATCH * NOUT * (FD / 4);
    if (t >= total) return;
    const int q = t & 15;
    const int o = (t >> 4) & (NOUT - 1);
    const int b = t >> 7;
    const size_t src = (size_t)b * (NF * FD) + (size_t)oidx[o] * FD + q * 4;
    reinterpret_cast<float4*>(out)[t] = *reinterpret_cast<const float4*>(x + src);
}

extern "C" void kernel_launch(void* const* d_in, const int* in_sizes, int n_in,
                              void* d_out, int out_size)
{
    const float* in_graph = (const float*)d_in[0];
    const float* weights  = (const float*)d_in[1];
    const int*   fold_idx = (const int*)d_in[2];
    const int*   out_idx  = (const int*)d_in[3];
    float*       out      = (float*)d_out;

    float *p0 = nullptr, *p1 = nullptr;
    uint4 *wh = nullptr, *wl = nullptr;
    cudaGetSymbolAddress((void**)&p0, g_x0);
    cudaGetSymbolAddress((void**)&p1, g_x1);
    cudaGetSymbolAddress((void**)&wh, g_wh);
    cudaGetSymbolAddress((void**)&wl, g_wl);

    cudaFuncSetAttribute(layer_mma_kernel,
                         cudaFuncAttributeMaxDynamicSharedMemorySize, SMEM_BYTES);

    // Pre-split + transpose all layer weights into bf16 hi/lo
    wprep_kernel<<<4 * 512, 256>>>(weights);

    const size_t wlayer   = (size_t)512 * 512;   // uint4 per layer
    const size_t i_stride = (size_t)NF * 2;      // ints per layer

    dim3 grid(NF, (BATCH / BM) / NT);            // (512, 4)
    dim3 block(256);

    layer_mma_kernel<<<grid, block, SMEM_BYTES>>>(in_graph, wh + 0 * wlayer, wl + 0 * wlayer,
                                                  fold_idx + 0 * i_stride, p0);
    layer_mma_kernel<<<grid, block, SMEM_BYTES>>>(p0, wh + 1 * wlayer, wl + 1 * wlayer,
                                                  fold_idx + 1 * i_stride, p1);
    layer_mma_kernel<<<grid, block, SMEM_BYTES>>>(p1, wh + 2 * wlayer, wl + 2 * wlayer,
                                                  fold_idx + 2 * i_stride, p0);
    layer_mma_kernel<<<grid, block, SMEM_BYTES>>>(p0, wh + 3 * wlayer, wl + 3 * wlayer,
                                                  fold_idx + 3 * i_stride, p1);

    const int total = BATCH * NOUT * (FD / 4);
    gather_kernel<<<(total + 255) / 256, 256>>>(p1, out_idx, out);
}

// round 11
// speedup vs baseline: 1.2424x; 1.1326x over previous
#include <cuda_runtime.h>
#include <cuda_bf16.h>
#include <cstdint>

// Problem constants
constexpr int BATCH = 2048;
constexpr int NF    = 512;
constexpr int FD    = 64;
constexpr int NOUT  = 8;
constexpr int BM    = 128;   // M-tile per block-iteration
constexpr int NT    = 4;     // m-tiles per CTA

// fp32 activation ping-pong (2 x 256 MB)
__device__ __align__(256) float g_x0[BATCH * NF * FD];
__device__ __align__(256) float g_x1[BATCH * NF * FD];
// Pre-split transposed weights: Wt[n][k] = W[k][n], bf16 hi/lo planes.
__device__ __align__(256) uint4 g_wh[4 * 512 * 512];
__device__ __align__(256) uint4 g_wl[4 * 512 * 512];

// SW128 swizzle (Swizzle<3,4,3>) on byte offsets with 128B rows
#define SW(o) ((o) ^ ((((unsigned)(o)) >> 3) & 0x70))

__device__ __forceinline__ uint32_t smem_u32(const void* p) {
    uint32_t a;
    asm("{ .reg .u64 t; cvta.to.shared.u64 t, %1; cvt.u32.u64 %0, t; }" : "=r"(a) : "l"(p));
    return a;
}
__device__ __forceinline__ uint32_t pack_hi_lo(float a, float b, uint32_t& lo) {
    __nv_bfloat162 h2 = __floats2bfloat162_rn(a, b);
    float ra = a - __bfloat162float(h2.x);
    float rb = b - __bfloat162float(h2.y);
    __nv_bfloat162 l2 = __floats2bfloat162_rn(ra, rb);
    lo = *reinterpret_cast<uint32_t*>(&l2);
    return *reinterpret_cast<uint32_t*>(&h2);
}
__device__ __forceinline__ void ldsm_x4(uint32_t* r, uint32_t addr) {
    asm volatile("ldmatrix.sync.aligned.m8n8.x4.shared.b16 {%0,%1,%2,%3}, [%4];"
                 : "=r"(r[0]), "=r"(r[1]), "=r"(r[2]), "=r"(r[3]) : "r"(addr));
}
__device__ __forceinline__ void mma_bf16(float* c, const uint32_t* a,
                                         uint32_t b0, uint32_t b1) {
    asm volatile(
        "mma.sync.aligned.m16n8k16.row.col.f32.bf16.bf16.f32 "
        "{%0,%1,%2,%3}, {%4,%5,%6,%7}, {%8,%9}, {%0,%1,%2,%3};"
        : "+f"(c[0]), "+f"(c[1]), "+f"(c[2]), "+f"(c[3])
        : "r"(a[0]), "r"(a[1]), "r"(a[2]), "r"(a[3]), "r"(b0), "r"(b1));
}
__device__ __forceinline__ void cp_async16(uint32_t dst, const void* src) {
    asm volatile("cp.async.cg.shared.global [%0], [%1], 16;" :: "r"(dst), "l"(src));
}
__device__ __forceinline__ void cp_commit() {
    asm volatile("cp.async.commit_group;");
}
__device__ __forceinline__ void cp_wait0() {
    asm volatile("cp.async.wait_group 0;");
}

// ---------------- weight prep: transpose + bf16 hi/lo split ----------------
__global__ void wprep_kernel(const float* __restrict__ W) {
    __shared__ float s[64][65];
    const int lf = blockIdx.x;                 // layer*512 + fold
    const float4* Wf4 = reinterpret_cast<const float4*>(W + (size_t)lf * 4096);
    for (int i = threadIdx.x; i < 1024; i += 256) {
        const int k = i >> 4, nq = i & 15;
        float4 v = Wf4[i];
        s[k][nq * 4 + 0] = v.x; s[k][nq * 4 + 1] = v.y;
        s[k][nq * 4 + 2] = v.z; s[k][nq * 4 + 3] = v.w;
    }
    __syncthreads();
    for (int i = threadIdx.x; i < 512; i += 256) {
        const int n = i >> 3, kq = i & 7;
        uint32_t hw[4], lw[4];
        #pragma unroll
        for (int j = 0; j < 4; j++) {
            const float a = s[kq * 8 + j * 2 + 0][n];
            const float b = s[kq * 8 + j * 2 + 1][n];
            hw[j] = pack_hi_lo(a, b, lw[j]);
        }
        g_wh[(size_t)lf * 512 + i] = make_uint4(hw[0], hw[1], hw[2], hw[3]);
        g_wl[(size_t)lf * 512 + i] = make_uint4(lw[0], lw[1], lw[2], lw[3]);
    }
}

// ---------------- pipelined HMMA layer kernel ------------------------------
// SMEM (bytes): HH 0 (16K), HL 16384 (16K), WH 32768 (8K), WL 40960 (8K),
//               RAW0 49152 (32K), RAW1 81920 (32K). Total 114688 (112K).
constexpr int SM_HH = 0, SM_HL = 16384, SM_WH = 32768, SM_WL = 40960;
constexpr int SM_R0 = 49152, SM_R1 = 81920;
constexpr int SMEM_BYTES = 114688;

__global__ __launch_bounds__(256, 2)
void layer_mma_kernel(const float* __restrict__ xin,
                      const uint4* __restrict__ wh,
                      const uint4* __restrict__ wl,
                      const int*   __restrict__ fidx,
                      float*       __restrict__ xout)
{
    extern __shared__ char smem[];
    const uint32_t sb = smem_u32(smem);
    const int tid = threadIdx.x, wid = tid >> 5, lid = tid & 31;
    const int f = blockIdx.x;

    const float* x0 = xin + (size_t)fidx[2 * f + 0] * FD;
    const float* x1 = xin + (size_t)fidx[2 * f + 1] * FD;

    // --- prologue: stage raw tile 0 via cp.async (overlaps W load below) ---
    // chunk c = j*256 + tid : row m = c>>4 (0..127), 16B quad q2 = c&15.
    {
        const int m0 = blockIdx.y * BM;        // t = 0
        #pragma unroll
        for (int j = 0; j < 8; j++) {
            const int c = j * 256 + tid;
            const int m = c >> 4, q2 = c & 15;
            const uint32_t doff = (uint32_t)(m * 256 + q2 * 16);
            const size_t goff = (size_t)(m0 + m) * (NF * FD) + q2 * 4;
            cp_async16(sb + SM_R0 + doff, x0 + goff);
            cp_async16(sb + SM_R1 + doff, x1 + goff);
        }
        cp_commit();
    }

    // --- W tiles: copy with SW128 swizzle, once ---
    const uint4* whf = wh + (size_t)f * 512;
    const uint4* wlf = wl + (size_t)f * 512;
    #pragma unroll
    for (int it = 0; it < 2; it++) {
        const int i = it * 256 + tid;
        const int n = i >> 3, q = i & 7;
        const uint32_t off = SW(n * 128 + q * 16);
        *reinterpret_cast<uint4*>(smem + SM_WH + off) = whf[i];
        *reinterpret_cast<uint4*>(smem + SM_WL + off) = wlf[i];
    }
    __syncthreads();

    const int wm = wid >> 1, wn = wid & 1;
    const int l7 = lid & 7, l8 = (lid >> 3) & 1, l16 = lid >> 4;

    // --- B fragments in registers (once per fold) ---
    uint32_t BH[4][2][4], BL[4][2][4];
    #pragma unroll
    for (int ks = 0; ks < 4; ks++) {
        const int kc = ks * 16 + l16 * 8;
        #pragma unroll
        for (int h = 0; h < 2; h++) {
            const int n = wn * 32 + h * 16 + l7 + l8 * 8;
            const uint32_t off = SW(n * 128 + kc * 2);
            ldsm_x4(BH[ks][h], sb + SM_WH + off);
            ldsm_x4(BL[ks][h], sb + SM_WL + off);
        }
    }

    cp_wait0();
    __syncthreads();                           // raw tile 0 visible to all

    const int quad = lid >> 2, qlane = lid & 3;

    #pragma unroll 1
    for (int t = 0; t < NT; t++) {
        const int m0 = blockIdx.y * BM + t * 512;

        // --- convert: raw smem -> H bf16 hi/lo planes (LDS-based, fast) ---
        #pragma unroll
        for (int it = 0; it < 4; it++) {
            const int i = it * 256 + tid;      // 0..1023
            const int m = i >> 3, q = i & 7;   // row m, 8-float chunk q (32B)
            const uint32_t roff = (uint32_t)(m * 256 + q * 32);
            const float4 a0 = *reinterpret_cast<const float4*>(smem + SM_R0 + roff);
            const float4 a1 = *reinterpret_cast<const float4*>(smem + SM_R0 + roff + 16);
            const float4 b0 = *reinterpret_cast<const float4*>(smem + SM_R1 + roff);
            const float4 b1 = *reinterpret_cast<const float4*>(smem + SM_R1 + roff + 16);
            const float p[8] = { a0.x * b0.x, a0.y * b0.y, a0.z * b0.z, a0.w * b0.w,
                                 a1.x * b1.x, a1.y * b1.y, a1.z * b1.z, a1.w * b1.w };
            uint32_t hw[4], lw[4];
            #pragma unroll
            for (int j = 0; j < 4; j++)
                hw[j] = pack_hi_lo(p[2 * j], p[2 * j + 1], lw[j]);
            const uint32_t off = SW(m * 128 + q * 16);
            *reinterpret_cast<uint4*>(smem + SM_HH + off) = make_uint4(hw[0], hw[1], hw[2], hw[3]);
            *reinterpret_cast<uint4*>(smem + SM_HL + off) = make_uint4(lw[0], lw[1], lw[2], lw[3]);
        }
        __syncthreads();                       // H visible; raw reads complete

        // --- issue cp.async for tile t+1 (overlaps with MMA below) ---
        if (t + 1 < NT) {
            const int mn = blockIdx.y * BM + (t + 1) * 512;
            #pragma unroll
            for (int j = 0; j < 8; j++) {
                const int c = j * 256 + tid;
                const int m = c >> 4, q2 = c & 15;
                const uint32_t doff = (uint32_t)(m * 256 + q2 * 16);
                const size_t goff = (size_t)(mn + m) * (NF * FD) + q2 * 4;
                cp_async16(sb + SM_R0 + doff, x0 + goff);
                cp_async16(sb + SM_R1 + doff, x1 + goff);
            }
            cp_commit();
        }

        // --- warp-tiled MMA: 32(M) x 32(N), B from registers ---
        float acc[2][4][4];
        #pragma unroll
        for (int mt = 0; mt < 2; mt++)
            #pragma unroll
            for (int nt = 0; nt < 4; nt++)
                #pragma unroll
                for (int j = 0; j < 4; j++)
                    acc[mt][nt][j] = 0.0f;

        #pragma unroll
        for (int ks = 0; ks < 4; ks++) {
            const int kc = ks * 16 + l16 * 8;
            uint32_t AH[2][4], AL[2][4];
            #pragma unroll
            for (int mt = 0; mt < 2; mt++) {
                const int row = wm * 32 + mt * 16 + l7 + l8 * 8;
                const uint32_t off = SW(row * 128 + kc * 2);
                ldsm_x4(AH[mt], sb + SM_HH + off);
                ldsm_x4(AL[mt], sb + SM_HL + off);
            }
            #pragma unroll
            for (int mt = 0; mt < 2; mt++)
                #pragma unroll
                for (int nt = 0; nt < 4; nt++) {
                    const int h = nt >> 1, s = nt & 1;
                    mma_bf16(acc[mt][nt], AH[mt], BH[ks][h][s], BH[ks][h][s + 2]);
                    mma_bf16(acc[mt][nt], AH[mt], BL[ks][h][s], BL[ks][h][s + 2]);
                    mma_bf16(acc[mt][nt], AL[mt], BH[ks][h][s], BH[ks][h][s + 2]);
                }
        }

        // --- epilogue: fragment -> GMEM ---
        #pragma unroll
        for (int mt = 0; mt < 2; mt++) {
            const int r = m0 + wm * 32 + mt * 16 + quad;
            #pragma unroll
            for (int nt = 0; nt < 4; nt++) {
                const int col = f * FD + wn * 32 + nt * 8 + qlane * 2;
                float* d0 = xout + (size_t)r * (NF * FD) + col;
                float* d1 = d0 + (size_t)8 * (NF * FD);
                *reinterpret_cast<float2*>(d0) = make_float2(acc[mt][nt][0], acc[mt][nt][1]);
                *reinterpret_cast<float2*>(d1) = make_float2(acc[mt][nt][2], acc[mt][nt][3]);
            }
        }

        if (t + 1 < NT) {
            cp_wait0();
            __syncthreads();                   // raw t+1 arrived; H reads done
        }
    }
}

// Final gather: out[b, o, :] = x[b, out_idx[o], :]
__global__ void gather_kernel(const float* __restrict__ x,
                              const int* __restrict__ oidx,
                              float* __restrict__ out)
{
    const int t = blockIdx.x * blockDim.x + threadIdx.x;
    const int total = BATCH * NOUT * (FD / 4);
    if (t >= total) return;
    const int q = t & 15;
    const int o = (t >> 4) & (NOUT - 1);
    const int b = t >> 7;
    const size_t src = (size_t)b * (NF * FD) + (size_t)oidx[o] * FD + q * 4;
    reinterpret_cast<float4*>(out)[t] = *reinterpret_cast<const float4*>(x + src);
}

extern "C" void kernel_launch(void* const* d_in, const int* in_sizes, int n_in,
                              void* d_out, int out_size)
{
    const float* in_graph = (const float*)d_in[0];
    const float* weights  = (const float*)d_in[1];
    const int*   fold_idx = (const int*)d_in[2];
    const int*   out_idx  = (const int*)d_in[3];
    float*       out      = (float*)d_out;

    float *p0 = nullptr, *p1 = nullptr;
    uint4 *wh = nullptr, *wl = nullptr;
    cudaGetSymbolAddress((void**)&p0, g_x0);
    cudaGetSymbolAddress((void**)&p1, g_x1);
    cudaGetSymbolAddress((void**)&wh, g_wh);
    cudaGetSymbolAddress((void**)&wl, g_wl);

    cudaFuncSetAttribute(layer_mma_kernel,
                         cudaFuncAttributeMaxDynamicSharedMemorySize, SMEM_BYTES);

    wprep_kernel<<<4 * 512, 256>>>(weights);

    const size_t wlayer   = (size_t)512 * 512;
    const size_t i_stride = (size_t)NF * 2;

    dim3 grid(NF, (BATCH / BM) / NT);            // (512, 4)
    dim3 block(256);

    layer_mma_kernel<<<grid, block, SMEM_BYTES>>>(in_graph, wh + 0 * wlayer, wl + 0 * wlayer,
                                                  fold_idx + 0 * i_stride, p0);
    layer_mma_kernel<<<grid, block, SMEM_BYTES>>>(p0, wh + 1 * wlayer, wl + 1 * wlayer,
                                                  fold_idx + 1 * i_stride, p1);
    layer_mma_kernel<<<grid, block, SMEM_BYTES>>>(p1, wh + 2 * wlayer, wl + 2 * wlayer,
                                                  fold_idx + 2 * i_stride, p0);
    layer_mma_kernel<<<grid, block, SMEM_BYTES>>>(p0, wh + 3 * wlayer, wl + 3 * wlayer,
                                                  fold_idx + 3 * i_stride, p1);

    const int total = BATCH * NOUT * (FD / 4);
    gather_kernel<<<(total + 255) / 256, 256>>>(p1, out_idx, out);
}

// round 12
// speedup vs baseline: 1.2768x; 1.0277x over previous
#include <cuda_runtime.h>
#include <cuda_bf16.h>
#include <cstdint>

// Problem constants
constexpr int BATCH = 2048;
constexpr int NF    = 512;
constexpr int FD    = 64;
constexpr int NOUT  = 8;
constexpr int BM    = 64;    // M-tile per iteration
constexpr int NT    = 8;     // m-tiles per CTA (pipelined)

// fp32 activation ping-pong (2 x 256 MB)
__device__ __align__(256) float g_x0[BATCH * NF * FD];
__device__ __align__(256) float g_x1[BATCH * NF * FD];
// Pre-split transposed weights: Wt[n][k] = W[k][n], bf16 hi/lo planes.
__device__ __align__(256) uint4 g_wh[4 * 512 * 512];
__device__ __align__(256) uint4 g_wl[4 * 512 * 512];

// SW128 swizzle (Swizzle<3,4,3>) on byte offsets with 128B rows
#define SW(o) ((o) ^ ((((unsigned)(o)) >> 3) & 0x70))

__device__ __forceinline__ uint32_t smem_u32(const void* p) {
    uint32_t a;
    asm("{ .reg .u64 t; cvta.to.shared.u64 t, %1; cvt.u32.u64 %0, t; }" : "=r"(a) : "l"(p));
    return a;
}
__device__ __forceinline__ uint32_t pack_hi_lo(float a, float b, uint32_t& lo) {
    __nv_bfloat162 h2 = __floats2bfloat162_rn(a, b);
    float ra = a - __bfloat162float(h2.x);
    float rb = b - __bfloat162float(h2.y);
    __nv_bfloat162 l2 = __floats2bfloat162_rn(ra, rb);
    lo = *reinterpret_cast<uint32_t*>(&l2);
    return *reinterpret_cast<uint32_t*>(&h2);
}
__device__ __forceinline__ void ldsm_x4(uint32_t* r, uint32_t addr) {
    asm volatile("ldmatrix.sync.aligned.m8n8.x4.shared.b16 {%0,%1,%2,%3}, [%4];"
                 : "=r"(r[0]), "=r"(r[1]), "=r"(r[2]), "=r"(r[3]) : "r"(addr));
}
__device__ __forceinline__ void mma_bf16(float* c, const uint32_t* a,
                                         uint32_t b0, uint32_t b1) {
    asm volatile(
        "mma.sync.aligned.m16n8k16.row.col.f32.bf16.bf16.f32 "
        "{%0,%1,%2,%3}, {%4,%5,%6,%7}, {%8,%9}, {%0,%1,%2,%3};"
        : "+f"(c[0]), "+f"(c[1]), "+f"(c[2]), "+f"(c[3])
        : "r"(a[0]), "r"(a[1]), "r"(a[2]), "r"(a[3]), "r"(b0), "r"(b1));
}
__device__ __forceinline__ void cp_async16(uint32_t dst, const void* src) {
    asm volatile("cp.async.cg.shared.global [%0], [%1], 16;" :: "r"(dst), "l"(src));
}
__device__ __forceinline__ void cp_commit() { asm volatile("cp.async.commit_group;"); }

// ---------------- weight prep: transpose + bf16 hi/lo split ----------------
__global__ void wprep_kernel(const float* __restrict__ W) {
    __shared__ float s[64][65];
    const int lf = blockIdx.x;
    const float4* Wf4 = reinterpret_cast<const float4*>(W + (size_t)lf * 4096);
    for (int i = threadIdx.x; i < 1024; i += 256) {
        const int k = i >> 4, nq = i & 15;
        float4 v = Wf4[i];
        s[k][nq * 4 + 0] = v.x; s[k][nq * 4 + 1] = v.y;
        s[k][nq * 4 + 2] = v.z; s[k][nq * 4 + 3] = v.w;
    }
    __syncthreads();
    for (int i = threadIdx.x; i < 512; i += 256) {
        const int n = i >> 3, kq = i & 7;
        uint32_t hw[4], lw[4];
        #pragma unroll
        for (int j = 0; j < 4; j++) {
            const float a = s[kq * 8 + j * 2 + 0][n];
            const float b = s[kq * 8 + j * 2 + 1][n];
            hw[j] = pack_hi_lo(a, b, lw[j]);
        }
        g_wh[(size_t)lf * 512 + i] = make_uint4(hw[0], hw[1], hw[2], hw[3]);
        g_wl[(size_t)lf * 512 + i] = make_uint4(lw[0], lw[1], lw[2], lw[3]);
    }
}

// ---------------- pipelined, interleaved HMMA layer kernel -----------------
// SMEM (bytes): WH 0 (8K), WL 8192 (8K),
//               H buffers: HH(b) = 16384 + b*16384, HL(b) = HH(b) + 8192,
//               raw: R(b, plane) = 49152 + b*32768 + plane*16384 (16K each).
// Total 114688 (112K) -> 2 CTAs/SM.
constexpr int SM_WH = 0, SM_WL = 8192;
constexpr int SM_H0 = 16384, SM_HSZ = 16384;
constexpr int SM_R0 = 49152, SM_RBUF = 32768, SM_RPL = 16384;
constexpr int SMEM_BYTES = 114688;

__global__ __launch_bounds__(256, 2)
void layer_mma_kernel(const float* __restrict__ xin,
                      const uint4* __restrict__ wh,
                      const uint4* __restrict__ wl,
                      const int*   __restrict__ fidx,
                      float*       __restrict__ xout)
{
    extern __shared__ char smem[];
    const uint32_t sb = smem_u32(smem);
    const int tid = threadIdx.x, wid = tid >> 5, lid = tid & 31;
    const int f = blockIdx.x;
    const int ybase = blockIdx.y * (NT * BM);

    const float* x0 = xin + (size_t)fidx[2 * f + 0] * FD;
    const float* x1 = xin + (size_t)fidx[2 * f + 1] * FD;

    // --- stage raw tiles 0 and 1 (each its own commit group) ---
    #pragma unroll
    for (int b = 0; b < 2; b++) {
        const int m0 = ybase + b * BM;
        #pragma unroll
        for (int j = 0; j < 4; j++) {
            const int c = j * 256 + tid;          // 0..1023
            const int m = c >> 4, q2 = c & 15;
            const uint32_t doff = (uint32_t)(m * 256 + q2 * 16);
            const size_t goff = (size_t)(m0 + m) * (NF * FD) + q2 * 4;
            cp_async16(sb + SM_R0 + b * SM_RBUF + doff, x0 + goff);
            cp_async16(sb + SM_R0 + b * SM_RBUF + SM_RPL + doff, x1 + goff);
        }
        cp_commit();
    }

    // --- W tiles: SW128 swizzled copy ---
    const uint4* whf = wh + (size_t)f * 512;
    const uint4* wlf = wl + (size_t)f * 512;
    #pragma unroll
    for (int it = 0; it < 2; it++) {
        const int i = it * 256 + tid;
        const int n = i >> 3, q = i & 7;
        const uint32_t off = SW(n * 128 + q * 16);
        *reinterpret_cast<uint4*>(smem + SM_WH + off) = whf[i];
        *reinterpret_cast<uint4*>(smem + SM_WL + off) = wlf[i];
    }
    __syncthreads();

    const int wm = wid >> 1;                   // 0..3 -> m offset wm*16
    const int wn = wid & 1;                    // 0..1 -> n offset wn*32
    const int l7 = lid & 7, l8 = (lid >> 3) & 1, l16 = lid >> 4;

    // --- B fragments in registers, once per fold (amortized over NT tiles) ---
    uint32_t BH[4][2][4], BL[4][2][4];
    #pragma unroll
    for (int ks = 0; ks < 4; ks++) {
        const int kc = ks * 16 + l16 * 8;
        #pragma unroll
        for (int h = 0; h < 2; h++) {
            const int n = wn * 32 + h * 16 + l7 + l8 * 8;
            const uint32_t off = SW(n * 128 + kc * 2);
            ldsm_x4(BH[ks][h], sb + SM_WH + off);
            ldsm_x4(BL[ks][h], sb + SM_WL + off);
        }
    }

    // --- drain raw0 (raw1 may stay in flight), convert tile 0 -> H[0] ---
    asm volatile("cp.async.wait_group 1;");
    __syncthreads();
    #pragma unroll
    for (int it = 0; it < 2; it++) {
        const int i = it * 256 + tid;             // 0..511
        const int m = i >> 3, q = i & 7;
        const uint32_t roff = (uint32_t)(m * 256 + q * 32);
        const char* ra = smem + SM_R0 + roff;
        const char* rb = smem + SM_R0 + SM_RPL + roff;
        const float4 a0 = *reinterpret_cast<const float4*>(ra);
        const float4 a1 = *reinterpret_cast<const float4*>(ra + 16);
        const float4 b0 = *reinterpret_cast<const float4*>(rb);
        const float4 b1 = *reinterpret_cast<const float4*>(rb + 16);
        const float p[8] = { a0.x * b0.x, a0.y * b0.y, a0.z * b0.z, a0.w * b0.w,
                             a1.x * b1.x, a1.y * b1.y, a1.z * b1.z, a1.w * b1.w };
        uint32_t hw[4], lw[4];
        #pragma unroll
        for (int j = 0; j < 4; j++) hw[j] = pack_hi_lo(p[2 * j], p[2 * j + 1], lw[j]);
        const uint32_t off = SW(m * 128 + q * 16);
        *reinterpret_cast<uint4*>(smem + SM_H0 + off) = make_uint4(hw[0], hw[1], hw[2], hw[3]);
        *reinterpret_cast<uint4*>(smem + SM_H0 + 8192 + off) = make_uint4(lw[0], lw[1], lw[2], lw[3]);
    }

    const int quad = lid >> 2, qlane = lid & 3;

    #pragma unroll 1
    for (int t = 0; t < NT; t++) {
        // 1. drain raw[t+1] (only group outstanding); 2. publish H[(t)%2] convert
        asm volatile("cp.async.wait_group 0;");
        __syncthreads();

        const int cur = t & 1, nxt = cur ^ 1;
        const uint32_t hh_c = sb + SM_H0 + cur * SM_HSZ;
        const uint32_t hl_c = hh_c + 8192;
        const int hh_n = SM_H0 + nxt * SM_HSZ;
        const int r_n  = SM_R0 + nxt * SM_RBUF;      // raw for tile t+1
        const bool do_conv = (t + 1 < NT);

        // 3. issue cp.async for tile t+2 into rbuf[cur] (its reads finished pre-sync)
        if (t + 2 < NT) {
            const int mn = ybase + (t + 2) * BM;
            #pragma unroll
            for (int j = 0; j < 4; j++) {
                const int c = j * 256 + tid;
                const int m = c >> 4, q2 = c & 15;
                const uint32_t doff = (uint32_t)(m * 256 + q2 * 16);
                const size_t goff = (size_t)(mn + m) * (NF * FD) + q2 * 4;
                cp_async16(sb + SM_R0 + cur * SM_RBUF + doff, x0 + goff);
                cp_async16(sb + SM_R0 + cur * SM_RBUF + SM_RPL + doff, x1 + goff);
            }
            cp_commit();
        }

        // 4+5. MMA on H[cur] interleaved with convert raw[nxt] -> H[nxt]
        const int m0 = ybase + t * BM;
        float acc[4][4];
        #pragma unroll
        for (int nt = 0; nt < 4; nt++)
            #pragma unroll
            for (int j = 0; j < 4; j++) acc[nt][j] = 0.0f;

        #pragma unroll
        for (int ks = 0; ks < 4; ks++) {
            const int kc = ks * 16 + l16 * 8;
            uint32_t AH[4], AL[4];
            {
                const int row = wm * 16 + l7 + l8 * 8;
                const uint32_t off = SW(row * 128 + kc * 2);
                ldsm_x4(AH, hh_c + off);
                ldsm_x4(AL, hl_c + off);
            }
            #pragma unroll
            for (int nt = 0; nt < 4; nt++) {
                const int h = nt >> 1, s = nt & 1;
                mma_bf16(acc[nt], AH, BH[ks][h][s], BH[ks][h][s + 2]);
                mma_bf16(acc[nt], AH, BL[ks][h][s], BL[ks][h][s + 2]);
                mma_bf16(acc[nt], AL, BH[ks][h][s], BH[ks][h][s + 2]);
            }
            // convert one item after ks=0 and ks=2 — fills issue slots under MMA
            if ((ks == 0 || ks == 2) && do_conv) {
                const int it = ks >> 1;
                const int i = it * 256 + tid;
                const int m = i >> 3, q = i & 7;
                const uint32_t roff = (uint32_t)(m * 256 + q * 32);
                const char* ra = smem + r_n + roff;
                const char* rb = smem + r_n + SM_RPL + roff;
                const float4 a0 = *reinterpret_cast<const float4*>(ra);
                const float4 a1 = *reinterpret_cast<const float4*>(ra + 16);
                const float4 b0 = *reinterpret_cast<const float4*>(rb);
                const float4 b1 = *reinterpret_cast<const float4*>(rb + 16);
                const float p[8] = { a0.x * b0.x, a0.y * b0.y, a0.z * b0.z, a0.w * b0.w,
                                     a1.x * b1.x, a1.y * b1.y, a1.z * b1.z, a1.w * b1.w };
                uint32_t hw[4], lw[4];
                #pragma unroll
                for (int j = 0; j < 4; j++) hw[j] = pack_hi_lo(p[2 * j], p[2 * j + 1], lw[j]);
                const uint32_t off = SW(m * 128 + q * 16);
                *reinterpret_cast<uint4*>(smem + hh_n + off) = make_uint4(hw[0], hw[1], hw[2], hw[3]);
                *reinterpret_cast<uint4*>(smem + hh_n + 8192 + off) = make_uint4(lw[0], lw[1], lw[2], lw[3]);
            }
        }

        // epilogue: fragment -> GMEM
        const int r = m0 + wm * 16 + quad;
        #pragma unroll
        for (int nt = 0; nt < 4; nt++) {
            const int col = f * FD + wn * 32 + nt * 8 + qlane * 2;
            float* d0 = xout + (size_t)r * (NF * FD) + col;
            float* d1 = d0 + (size_t)8 * (NF * FD);
            *reinterpret_cast<float2*>(d0) = make_float2(acc[nt][0], acc[nt][1]);
            *reinterpret_cast<float2*>(d1) = make_float2(acc[nt][2], acc[nt][3]);
        }
    }
}

// Final gather: out[b, o, :] = x[b, out_idx[o], :]
__global__ void gather_kernel(const float* __restrict__ x,
                              const int* __restrict__ oidx,
                              float* __restrict__ out)
{
    const int t = blockIdx.x * blockDim.x + threadIdx.x;
    const int total = BATCH * NOUT * (FD / 4);
    if (t >= total) return;
    const int q = t & 15;
    const int o = (t >> 4) & (NOUT - 1);
    const int b = t >> 7;
    const size_t src = (size_t)b * (NF * FD) + (size_t)oidx[o] * FD + q * 4;
    reinterpret_cast<float4*>(out)[t] = *reinterpret_cast<const float4*>(x + src);
}

extern "C" void kernel_launch(void* const* d_in, const int* in_sizes, int n_in,
                              void* d_out, int out_size)
{
    const float* in_graph = (const float*)d_in[0];
    const float* weights  = (const float*)d_in[1];
    const int*   fold_idx = (const int*)d_in[2];
    const int*   out_idx  = (const int*)d_in[3];
    float*       out      = (float*)d_out;

    float *p0 = nullptr, *p1 = nullptr;
    uint4 *wh = nullptr, *wl = nullptr;
    cudaGetSymbolAddress((void**)&p0, g_x0);
    cudaGetSymbolAddress((void**)&p1, g_x1);
    cudaGetSymbolAddress((void**)&wh, g_wh);
    cudaGetSymbolAddress((void**)&wl, g_wl);

    cudaFuncSetAttribute(layer_mma_kernel,
                         cudaFuncAttributeMaxDynamicSharedMemorySize, SMEM_BYTES);

    wprep_kernel<<<4 * 512, 256>>>(weights);

    const size_t wlayer   = (size_t)512 * 512;
    const size_t i_stride = (size_t)NF * 2;

    dim3 grid(NF, BATCH / (NT * BM));            // (512, 4)
    dim3 block(256);

    layer_mma_kernel<<<grid, block, SMEM_BYTES>>>(in_graph, wh + 0 * wlayer, wl + 0 * wlayer,
                                                  fold_idx + 0 * i_stride, p0);
    layer_mma_kernel<<<grid, block, SMEM_BYTES>>>(p0, wh + 1 * wlayer, wl + 1 * wlayer,
                                                  fold_idx + 1 * i_stride, p1);
    layer_mma_kernel<<<grid, block, SMEM_BYTES>>>(p1, wh + 2 * wlayer, wl + 2 * wlayer,
                                                  fold_idx + 2 * i_stride, p0);
    layer_mma_kernel<<<grid, block, SMEM_BYTES>>>(p0, wh + 3 * wlayer, wl + 3 * wlayer,
                                                  fold_idx + 3 * i_stride, p1);

    const int total = BATCH * NOUT * (FD / 4);
    gather_kernel<<<(total + 255) / 256, 256>>>(p1, out_idx, out);
}